// round 6
// baseline (speedup 1.0000x reference)
#include <cuda_runtime.h>
#include <cstdint>
#include <math.h>

#define TOK   8192
#define DIM   1024
#define HID   2048
#define NE    8
#define CAP   1280
#define MAXPE 2560   // 2*CAP, max entries per expert

#define BK      32
#define SROW    36                  // smem row stride in floats (conflict-free frag reads, 16B-aligned rows)
#define STAGEF  (256 * SROW)        // floats per stage (128 A rows + 128 B rows)
#define SMEMB   (2 * STAGEF * 4)    // dynamic smem bytes (73728)

// ---------------- scratch (device globals; no allocation) ----------------
__device__ int   g_cnt[NE];
__device__ int   g_topi[TOK * 2];
__device__ float g_topw[TOK * 2];
__device__ int   g_list[NE * MAXPE];
__device__ int   g_slot[TOK * 2];          // -1 = dropped, else e*MAXPE+pos
__device__ float g_act[(size_t)NE * MAXPE * HID];  // ~168 MB
__device__ float g_y [(size_t)NE * MAXPE * DIM];   // ~84 MB

// ---------------- helpers ----------------
__device__ __forceinline__ uint32_t f2tf(float x) {
    uint32_t r;
    asm("cvt.rna.tf32.f32 %0, %1;" : "=r"(r) : "f"(x));
    return r;
}

__device__ __forceinline__ void mma8(float c[4], const uint32_t a[4], const uint32_t b[2]) {
    asm volatile(
        "mma.sync.aligned.m16n8k8.row.col.f32.tf32.tf32.f32 "
        "{%0,%1,%2,%3},{%4,%5,%6,%7},{%8,%9},{%0,%1,%2,%3};"
        : "+f"(c[0]), "+f"(c[1]), "+f"(c[2]), "+f"(c[3])
        : "r"(a[0]), "r"(a[1]), "r"(a[2]), "r"(a[3]), "r"(b[0]), "r"(b[1]));
}

__device__ __forceinline__ void cp16(uint32_t dst, const void* src, bool valid) {
    int sz = valid ? 16 : 0;
    asm volatile("cp.async.cg.shared.global [%0], [%1], 16, %2;\n"
                 :: "r"(dst), "l"(src), "r"(sz));
}
__device__ __forceinline__ void cp_commit() { asm volatile("cp.async.commit_group;\n"); }
template <int N>
__device__ __forceinline__ void cp_wait() { asm volatile("cp.async.wait_group %0;\n" :: "n"(N)); }

__device__ __forceinline__ float silu_f(float g) {
    return g / (1.0f + expf(-g));
}

// ---------------- 0: zero counters ----------------
__global__ void zero_cnt_kernel() {
    if (threadIdx.x < NE) g_cnt[threadIdx.x] = 0;
}

// ---------------- 1: router ----------------
__global__ void router_kernel(const float* __restrict__ x, const float* __restrict__ gw) {
    __shared__ float4 sgw[NE * 256];
    int tid = threadIdx.x;
    for (int i = tid; i < NE * 256; i += 256) sgw[i] = ((const float4*)gw)[i];
    __syncthreads();

    int lane = tid & 31, w = tid >> 5;
    int t = blockIdx.x * 8 + w;
    const float4* xr = (const float4*)(x + (size_t)t * DIM);

    float acc[NE];
#pragma unroll
    for (int e = 0; e < NE; e++) acc[e] = 0.0f;

    for (int i = lane; i < DIM / 4; i += 32) {
        float4 xv = xr[i];
#pragma unroll
        for (int e = 0; e < NE; e++) {
            float4 g = sgw[e * 256 + i];
            acc[e] += xv.x * g.x + xv.y * g.y + xv.z * g.z + xv.w * g.w;
        }
    }
#pragma unroll
    for (int off = 16; off; off >>= 1)
#pragma unroll
        for (int e = 0; e < NE; e++) acc[e] += __shfl_down_sync(0xffffffffu, acc[e], off);

    if (lane == 0) {
        float mx = acc[0];
#pragma unroll
        for (int e = 1; e < NE; e++) mx = fmaxf(mx, acc[e]);
        float ex[NE], Z = 0.0f;
#pragma unroll
        for (int e = 0; e < NE; e++) { ex[e] = expf(acc[e] - mx); Z += ex[e]; }

        int i1 = 0; float p1 = ex[0];
#pragma unroll
        for (int e = 1; e < NE; e++) if (ex[e] > p1) { p1 = ex[e]; i1 = e; }
        int i2 = -1; float p2 = -1.0f;
#pragma unroll
        for (int e = 0; e < NE; e++) if (e != i1 && ex[e] > p2) { p2 = ex[e]; i2 = e; }

        p1 /= Z; p2 /= Z;
        float s = p1 + p2 + 1e-9f;
        g_topi[t * 2 + 0] = i1;
        g_topi[t * 2 + 1] = i2;
        g_topw[t * 2 + 0] = p1 / s;
        g_topw[t * 2 + 1] = p2 / s;
    }
}

// ---------------- 2: exact token-order capacity scan ----------------
__global__ void scan_kernel() {
    int b = blockIdx.x;
    int k = b >> 3, e = b & 7;
    __shared__ int warp_tot[8];
    __shared__ int warp_off[8];
    __shared__ int blk_tot;
    int tid = threadIdx.x, lane = tid & 31, w = tid >> 5;
    int base = 0;

    for (int c0 = 0; c0 < TOK; c0 += 256) {
        int t = c0 + tid;
        bool flag = (g_topi[t * 2 + k] == e);
        unsigned m = __ballot_sync(0xffffffffu, flag);
        int pre = __popc(m & ((1u << lane) - 1u));
        if (lane == 0) warp_tot[w] = __popc(m);
        __syncthreads();
        if (tid == 0) {
            int s = 0;
#pragma unroll
            for (int i = 0; i < 8; i++) { warp_off[i] = s; s += warp_tot[i]; }
            blk_tot = s;
        }
        __syncthreads();
        if (flag) {
            int rank = base + warp_off[w] + pre;
            if (rank < CAP) {
                int pos = atomicAdd(&g_cnt[e], 1);
                g_list[e * MAXPE + pos] = t;
                g_slot[t * 2 + k] = e * MAXPE + pos;
            } else {
                g_slot[t * 2 + k] = -1;
            }
        }
        base += blk_tot;
        __syncthreads();
    }
}

// ---------------- 3: fused gate+up GEMM ----------------
// Block tile M=128 x N=128 (interleaved: smem B row rbi = 2*c + s, s=0 gate / 1 up,
// c = local output column 0..63). 4 warps, warp tile 64x64, BK=32, 2-stage cp.async.
// Epilogue: each thread's mma c-pair (even,odd) = (g_c, u_c) -> act = silu(g)*u.
__global__ __launch_bounds__(128) void gemm_gateup_kernel(
    const float* __restrict__ x,
    const float* __restrict__ Wg,
    const float* __restrict__ Wu)
{
    extern __shared__ float smem[];
    int e = blockIdx.z;
    int cnt = g_cnt[e];
    int m0 = blockIdx.x * 128;
    if (m0 >= cnt) return;
    int n0 = blockIdx.y * 64;   // actual output column base

    int tid = threadIdx.x, lane = tid & 31, w = tid >> 5;
    int wm = w >> 1, wn = w & 1;

    uint32_t smem_u = (uint32_t)__cvta_generic_to_shared(smem);

    // A: thread loads full row `tid` (128B = 8 x 16B), gathered via token list
    int mrow = m0 + tid;
    bool avalid = (mrow < cnt);
    int atok = avalid ? g_list[e * MAXPE + mrow] : 0;
    const float* asrc = x + (size_t)atok * DIM;

    // B: thread loads full smem row rbi = tid: col = n0 + (tid>>1), src = tid&1 ? Wu : Wg
    int bcol = n0 + (tid >> 1);
    const float* bsrc = ((tid & 1) ? Wu : Wg) + ((size_t)e * HID + bcol) * DIM;

    float acc[4][8][4];
#pragma unroll
    for (int mt = 0; mt < 4; mt++)
#pragma unroll
        for (int nt = 0; nt < 8; nt++)
#pragma unroll
            for (int r = 0; r < 4; r++) acc[mt][nt][r] = 0.0f;

    auto issue = [&](int s, int k0) {
        uint32_t ab = smem_u + s * (STAGEF * 4) + tid * (SROW * 4);
        const float* ap = asrc + k0;
#pragma unroll
        for (int seg = 0; seg < 8; seg++) cp16(ab + seg * 16, ap + seg * 4, avalid);
        uint32_t bb = smem_u + s * (STAGEF * 4) + (128 + tid) * (SROW * 4);
        const float* bp = bsrc + k0;
#pragma unroll
        for (int seg = 0; seg < 8; seg++) cp16(bb + seg * 16, bp + seg * 4, true);
    };

    auto compute = [&](int s) {
        const float* As = smem + s * STAGEF;
        const float* Bs = As + 128 * SROW;
#pragma unroll
        for (int ks = 0; ks < 4; ks++) {
            uint32_t a[4][4];
#pragma unroll
            for (int mt = 0; mt < 4; mt++) {
                int r = wm * 64 + mt * 16 + (lane >> 2);
                int c = ks * 8 + (lane & 3);
                a[mt][0] = f2tf(As[r * SROW + c]);
                a[mt][1] = f2tf(As[(r + 8) * SROW + c]);
                a[mt][2] = f2tf(As[r * SROW + c + 4]);
                a[mt][3] = f2tf(As[(r + 8) * SROW + c + 4]);
            }
            uint32_t b[8][2];
#pragma unroll
            for (int nt = 0; nt < 8; nt++) {
                int n = wn * 64 + nt * 8 + (lane >> 2);
                int c = ks * 8 + (lane & 3);
                b[nt][0] = f2tf(Bs[n * SROW + c]);
                b[nt][1] = f2tf(Bs[n * SROW + c + 4]);
            }
#pragma unroll
            for (int mt = 0; mt < 4; mt++)
#pragma unroll
                for (int nt = 0; nt < 8; nt++)
                    mma8(acc[mt][nt], a[mt], b[nt]);
        }
    };

    issue(0, 0); cp_commit();
    const int NT = DIM / BK;  // 32
    for (int kt = 0; kt < NT; kt++) {
        if (kt + 1 < NT) {
            issue((kt + 1) & 1, (kt + 1) * BK); cp_commit();
            cp_wait<1>();
        } else {
            cp_wait<0>();
        }
        __syncthreads();
        compute(kt & 1);
        __syncthreads();
    }

    // epilogue: interleaved pair (even,odd) = (g,u) for column c
    float* actb = g_act + (size_t)e * MAXPE * HID;
#pragma unroll
    for (int mt = 0; mt < 4; mt++) {
        int rbase = m0 + wm * 64 + mt * 16 + (lane >> 2);
#pragma unroll
        for (int nt = 0; nt < 8; nt++) {
            int c = n0 + wn * 32 + nt * 4 + (lane & 3);
#pragma unroll
            for (int h = 0; h < 2; h++) {
                int r = rbase + 8 * h;
                if (r < cnt) {
                    float g = acc[mt][nt][2 * h];
                    float u = acc[mt][nt][2 * h + 1];
                    actb[(size_t)r * HID + c] = silu_f(g) * u;
                }
            }
        }
    }
}

// ---------------- 4: down GEMM ----------------
// Block tile M=128 x N=128, K=HID, same pipeline. A = g_act rows (dense, rows>=cnt are 0).
__global__ __launch_bounds__(128) void gemm_down_kernel(const float* __restrict__ Wd)
{
    extern __shared__ float smem[];
    int e = blockIdx.z;
    int cnt = g_cnt[e];
    int m0 = blockIdx.x * 128;
    if (m0 >= cnt) return;
    int n0 = blockIdx.y * 128;

    int tid = threadIdx.x, lane = tid & 31, w = tid >> 5;
    int wm = w >> 1, wn = w & 1;

    uint32_t smem_u = (uint32_t)__cvta_generic_to_shared(smem);

    const float* asrc = g_act + (size_t)e * MAXPE * HID + (size_t)(m0 + tid) * HID;
    const float* bsrc = Wd + ((size_t)e * DIM + n0 + tid) * HID;

    float acc[4][8][4];
#pragma unroll
    for (int mt = 0; mt < 4; mt++)
#pragma unroll
        for (int nt = 0; nt < 8; nt++)
#pragma unroll
            for (int r = 0; r < 4; r++) acc[mt][nt][r] = 0.0f;

    auto issue = [&](int s, int k0) {
        uint32_t ab = smem_u + s * (STAGEF * 4) + tid * (SROW * 4);
        const float* ap = asrc + k0;
#pragma unroll
        for (int seg = 0; seg < 8; seg++) cp16(ab + seg * 16, ap + seg * 4, true);
        uint32_t bb = smem_u + s * (STAGEF * 4) + (128 + tid) * (SROW * 4);
        const float* bp = bsrc + k0;
#pragma unroll
        for (int seg = 0; seg < 8; seg++) cp16(bb + seg * 16, bp + seg * 4, true);
    };

    auto compute = [&](int s) {
        const float* As = smem + s * STAGEF;
        const float* Bs = As + 128 * SROW;
#pragma unroll
        for (int ks = 0; ks < 4; ks++) {
            uint32_t a[4][4];
#pragma unroll
            for (int mt = 0; mt < 4; mt++) {
                int r = wm * 64 + mt * 16 + (lane >> 2);
                int c = ks * 8 + (lane & 3);
                a[mt][0] = f2tf(As[r * SROW + c]);
                a[mt][1] = f2tf(As[(r + 8) * SROW + c]);
                a[mt][2] = f2tf(As[r * SROW + c + 4]);
                a[mt][3] = f2tf(As[(r + 8) * SROW + c + 4]);
            }
            uint32_t b[8][2];
#pragma unroll
            for (int nt = 0; nt < 8; nt++) {
                int n = wn * 64 + nt * 8 + (lane >> 2);
                int c = ks * 8 + (lane & 3);
                b[nt][0] = f2tf(Bs[n * SROW + c]);
                b[nt][1] = f2tf(Bs[n * SROW + c + 4]);
            }
#pragma unroll
            for (int mt = 0; mt < 4; mt++)
#pragma unroll
                for (int nt = 0; nt < 8; nt++)
                    mma8(acc[mt][nt], a[mt], b[nt]);
        }
    };

    issue(0, 0); cp_commit();
    const int NT = HID / BK;  // 64
    for (int kt = 0; kt < NT; kt++) {
        if (kt + 1 < NT) {
            issue((kt + 1) & 1, (kt + 1) * BK); cp_commit();
            cp_wait<1>();
        } else {
            cp_wait<0>();
        }
        __syncthreads();
        compute(kt & 1);
        __syncthreads();
    }

    float* yb = g_y + (size_t)e * MAXPE * DIM;
#pragma unroll
    for (int mt = 0; mt < 4; mt++) {
        int rbase = m0 + wm * 64 + mt * 16 + (lane >> 2);
#pragma unroll
        for (int nt = 0; nt < 8; nt++) {
            int c = n0 + wn * 64 + nt * 8 + 2 * (lane & 3);
#pragma unroll
            for (int h = 0; h < 2; h++) {
                int r = rbase + 8 * h;
                if (r < cnt) {
                    float2 v = make_float2(acc[mt][nt][2 * h], acc[mt][nt][2 * h + 1]);
                    *(float2*)&yb[(size_t)r * DIM + c] = v;
                }
            }
        }
    }
}

// ---------------- 5: combine ----------------
__global__ void combine_kernel(float* __restrict__ out) {
    int t = blockIdx.x;
    int tid = threadIdx.x;
    int s0 = g_slot[t * 2 + 0];
    int s1 = g_slot[t * 2 + 1];
    float w0 = g_topw[t * 2 + 0];
    float w1 = g_topw[t * 2 + 1];

    const float4* y4 = (const float4*)g_y;
    float4 r = make_float4(0.f, 0.f, 0.f, 0.f);
    int c4 = tid;  // 256 threads * 4 floats = 1024 = DIM
    if (s0 >= 0) {
        float4 v = y4[(size_t)s0 * (DIM / 4) + c4];
        r.x += w0 * v.x; r.y += w0 * v.y; r.z += w0 * v.z; r.w += w0 * v.w;
    }
    if (s1 >= 0) {
        float4 v = y4[(size_t)s1 * (DIM / 4) + c4];
        r.x += w1 * v.x; r.y += w1 * v.y; r.z += w1 * v.z; r.w += w1 * v.w;
    }
    ((float4*)out)[(size_t)t * (DIM / 4) + c4] = r;
}

// ---------------- launch ----------------
extern "C" void kernel_launch(void* const* d_in, const int* in_sizes, int n_in,
                              void* d_out, int out_size) {
    const float* x  = (const float*)d_in[0];
    const float* gw = (const float*)d_in[1];
    const float* wg = (const float*)d_in[2];
    const float* wu = (const float*)d_in[3];
    const float* wd = (const float*)d_in[4];
    float* out = (float*)d_out;

    cudaFuncSetAttribute(gemm_gateup_kernel, cudaFuncAttributeMaxDynamicSharedMemorySize, SMEMB);
    cudaFuncSetAttribute(gemm_down_kernel,   cudaFuncAttributeMaxDynamicSharedMemorySize, SMEMB);

    zero_cnt_kernel<<<1, 32>>>();
    router_kernel<<<TOK / 8, 256>>>(x, gw);
    scan_kernel<<<16, 256>>>();
    gemm_gateup_kernel<<<dim3(MAXPE / 128, HID / 64, NE), 128, SMEMB>>>(x, wg, wu);
    gemm_down_kernel<<<dim3(MAXPE / 128, DIM / 128, NE), 128, SMEMB>>>(wd);
    combine_kernel<<<TOK, 256>>>(out);
}